// round 5
// baseline (speedup 1.0000x reference)
#include <cuda_runtime.h>
#include <cstdint>
#include <math.h>

// MultiVectorQuantizer: 4 groups, K=512 codes, D=128.
// Bit-replicates reference fp32 dist rounding via integer scores on the
// ulp(x_sq) grid (see R1-R3). GEMM uses packed fp32 FFMA2 (fma.rn.f32x2),
// which is lane-wise bit-identical to scalar FFMA in the same k-order.

#define TM 128          // tokens per CTA
#define NC 64           // codes per chunk
#define KD 128
#define KCODES 512
#define NTHREADS 128    // 16 token-slots x 8 code-slots, 8x8 tile each
#define MAGIC 12582912.0f   // 1.5 * 2^23 : add/sub forces RHE to integer

typedef unsigned long long ull;

__device__ double g_loss[4];
__device__ float  g_wsq[4 * KCODES];

struct SMem {
    double lred[4];
    float  X[KD][TM + 4];     // [d][token], stride 132
    float  W[KD][NC + 4];     // [d][code],  stride 68
    float  wsq[NC];
    float  invU[TM];          // 2^(23-E), E = exponent(x_sq)
    float  sc2[TM];           // 2^(24-E)
    float  t0[TM];            // (2^E - x_sq)*invU
    int    idx[TM];
};

__device__ __forceinline__ ull pk2(float lo, float hi) {
    ull r;
    asm("mov.b64 %0, {%1,%2};" : "=l"(r) : "f"(lo), "f"(hi));
    return r;
}
__device__ __forceinline__ void upk2(float& lo, float& hi, ull v) {
    asm("mov.b64 {%0,%1}, %2;" : "=f"(lo), "=f"(hi) : "l"(v));
}
__device__ __forceinline__ void fma2(ull& acc, ull a, ull b) {
    asm("fma.rn.f32x2 %0, %1, %2, %0;" : "+l"(acc) : "l"(a), "l"(b));
}

__global__ void prep_kernel(const float* __restrict__ w0, const float* __restrict__ w1,
                            const float* __restrict__ w2, const float* __restrict__ w3) {
    int i = blockIdx.x * blockDim.x + threadIdx.x;
    if (i < 4) g_loss[i] = 0.0;
    if (i < 4 * KCODES) {
        int g = i >> 9;
        int k = i & (KCODES - 1);
        const float* w = (g == 0) ? w0 : (g == 1) ? w1 : (g == 2) ? w2 : w3;
        const float4* row = reinterpret_cast<const float4*>(w + (size_t)k * KD);
        float s = 0.f;
        #pragma unroll 8
        for (int d = 0; d < KD / 4; d++) {
            float4 v = row[d];
            // sequential mul-then-add, exact order of jnp.sum(W*W)
            s = __fadd_rn(s, __fmul_rn(v.x, v.x));
            s = __fadd_rn(s, __fmul_rn(v.y, v.y));
            s = __fadd_rn(s, __fmul_rn(v.z, v.z));
            s = __fadd_rn(s, __fmul_rn(v.w, v.w));
        }
        g_wsq[i] = s;
    }
}

// round-half-even of (rc0 + t), rc0 integer-valued float, exact frac in t.
__device__ __forceinline__ float rne_adjust(float rc0, float t) {
    float inc = 0.f;
    if (t > 0.5f) inc = 1.f;
    else if (t < -0.5f) inc = -1.f;
    else if (t == 0.5f) {
        float h = __fmul_rn(__fadd_rn(rc0, 1.f), 0.5f);
        inc = (h == rintf(h)) ? 1.f : 0.f;
    } else if (t == -0.5f) {
        float h = __fmul_rn(__fsub_rn(rc0, 1.f), 0.5f);
        inc = (h == rintf(h)) ? -1.f : 0.f;
    }
    return rc0 + inc;
}

// magic-number RHE to integer (|x| < 2^22)
__device__ __forceinline__ float rhe_int(float x) {
    return __fsub_rn(__fadd_rn(x, MAGIC), MAGIC);
}

__global__ __launch_bounds__(NTHREADS, 2)
void vq_kernel(const float* __restrict__ lat,
               const float* __restrict__ w0, const float* __restrict__ w1,
               const float* __restrict__ w2, const float* __restrict__ w3,
               float* __restrict__ out) {
    extern __shared__ char smraw[];
    SMem& sm = *reinterpret_cast<SMem*>(smraw);

    const int g  = blockIdx.y;
    const int t0blk = blockIdx.x * TM;
    const float* __restrict__ wg = (g == 0) ? w0 : (g == 1) ? w1 : (g == 2) ? w2 : w3;
    const int tid = threadIdx.x;
    const int tc = tid & 7;         // code slot: codes tc*8 .. tc*8+7
    const int tr = tid >> 3;        // token slot: tokens tr*8 .. tr*8+7

    // ---- load X tile [128 tok x 128 d] -> transposed smem ----
    for (int i = tid; i < TM * 32; i += NTHREADS) {
        int tok = i >> 5;
        int d4  = i & 31;
        float4 v = *reinterpret_cast<const float4*>(
            lat + (size_t)(t0blk + tok) * 512 + (size_t)g * KD + d4 * 4);
        sm.X[d4 * 4 + 0][tok] = v.x;
        sm.X[d4 * 4 + 1][tok] = v.y;
        sm.X[d4 * 4 + 2][tok] = v.z;
        sm.X[d4 * 4 + 3][tok] = v.w;
    }
    __syncthreads();

    // ---- per-token binade constants ----
    {
        float s = 0.f;
        #pragma unroll 8
        for (int d = 0; d < KD; d++) {
            float v = sm.X[d][tid];
            s = fmaf(v, v, s);              // only the exponent matters
        }
        uint32_t b = __float_as_uint(s);
        uint32_t e = (b >> 23) & 0xFF;
        sm.invU[tid] = __uint_as_float((277u - e) << 23);
        sm.sc2[tid]  = __uint_as_float((278u - e) << 23);
        float pw     = __uint_as_float(e << 23);
        sm.t0[tid]   = __fmul_rn(__fsub_rn(pw, s), sm.invU[tid]);
    }

    float iUr[8], sc2r[8], tt0r[8];
    float best[8];
    int   bidx[8];
    #pragma unroll
    for (int r = 0; r < 8; r++) { best[r] = 3.4e38f; bidx[r] = 0; }
    bool got_const = false;

    for (int c = 0; c < KCODES / NC; c++) {
        __syncthreads();
        if (!got_const) {
            #pragma unroll
            for (int r = 0; r < 8; r++) {
                iUr[r]  = sm.invU[tr * 8 + r];
                sc2r[r] = sm.sc2[tr * 8 + r];
                tt0r[r] = sm.t0[tr * 8 + r];
            }
            got_const = true;
        }
        // ---- load W chunk [64 codes x 128 d] -> transposed smem ----
        for (int i = tid; i < NC * 32; i += NTHREADS) {
            int n  = i >> 5;
            int d4 = i & 31;
            float4 v = *reinterpret_cast<const float4*>(
                wg + (size_t)(c * NC + n) * KD + d4 * 4);
            sm.W[d4 * 4 + 0][n] = v.x;
            sm.W[d4 * 4 + 1][n] = v.y;
            sm.W[d4 * 4 + 2][n] = v.z;
            sm.W[d4 * 4 + 3][n] = v.w;
        }
        if (tid < NC) sm.wsq[tid] = g_wsq[g * KCODES + c * NC + tid];
        __syncthreads();

        // ---- 8x8 tile via FFMA2: acc2[p][j], p = token pair, j = code ----
        ull acc2[4][8];
        #pragma unroll
        for (int p = 0; p < 4; p++)
            #pragma unroll
            for (int j = 0; j < 8; j++) acc2[p][j] = 0ull;

        const float* xk = &sm.X[0][tr * 8];
        const float* wk = &sm.W[0][tc * 8];
        #pragma unroll 4
        for (int k = 0; k < KD; k++) {
            ulonglong2 av0 = *reinterpret_cast<const ulonglong2*>(xk);
            ulonglong2 av1 = *reinterpret_cast<const ulonglong2*>(xk + 4);
            float4 b0 = *reinterpret_cast<const float4*>(wk);
            float4 b1 = *reinterpret_cast<const float4*>(wk + 4);
            xk += TM + 4;
            wk += NC + 4;
            ull A[4] = {av0.x, av0.y, av1.x, av1.y};
            ull B[8] = {pk2(b0.x, b0.x), pk2(b0.y, b0.y), pk2(b0.z, b0.z), pk2(b0.w, b0.w),
                        pk2(b1.x, b1.x), pk2(b1.y, b1.y), pk2(b1.z, b1.z), pk2(b1.w, b1.w)};
            #pragma unroll
            for (int p = 0; p < 4; p++)
                #pragma unroll
                for (int j = 0; j < 8; j++)
                    fma2(acc2[p][j], A[p], B[j]);
        }

        // ---- integer-grid scoring (exact RHE, magic rounding) ----
        float wq8[8];
        #pragma unroll
        for (int j = 0; j < 8; j++) wq8[j] = sm.wsq[tc * 8 + j];

        #pragma unroll
        for (int p = 0; p < 4; p++) {
            #pragma unroll
            for (int h = 0; h < 2; h++) {
                int r = 2 * p + h;
                float iU = iUr[r], sc2v = sc2r[r], tt0 = tt0r[r];
                #pragma unroll
                for (int j = 0; j < 8; j++) {
                    float lo, hi;
                    upk2(lo, hi, acc2[p][j]);
                    float cr = h ? hi : lo;
                    int kg = c * NC + tc * 8 + j;
                    float m = rhe_int(__fmul_rn(wq8[j], iU));   // exact prod (pow2)
                    float z = __fmul_rn(cr, sc2v);              // exact
                    // TwoSum(m, -z)
                    float bn = -z;
                    float s  = __fadd_rn(m, bn);
                    float ap = __fsub_rn(s, bn);
                    float bp = __fsub_rn(s, ap);
                    float err = __fadd_rn(__fsub_rn(m, ap), __fsub_rn(bn, bp));
                    float rc0 = rhe_int(s);
                    float d   = __fsub_rn(s, rc0);
                    float t   = __fadd_rn(d, err);
                    float rc  = rne_adjust(rc0, t);
                    float score = rc;
                    if (rc <= tt0) {            // rare: dist below 2^E -> half grid
                        float s2 = __fadd_rn(s, s), e2 = __fadd_rn(err, err);
                        float rf0 = rhe_int(s2);
                        float d2  = __fsub_rn(s2, rf0);
                        float t2  = __fadd_rn(d2, e2);
                        float rf  = rne_adjust(rf0, t2);
                        rf = __fmul_rn(rf, 0.5f);
                        score = (rf < tt0) ? rf : rc;
                    }
                    if (score < best[r]) { best[r] = score; bidx[r] = kg; }
                }
            }
        }
    }

    // ---- argmin reduce across the 8 tc-lanes sharing this tr ----
    #pragma unroll
    for (int r = 0; r < 8; r++) {
        float s  = best[r];
        int   id = bidx[r];
        #pragma unroll
        for (int mk = 4; mk >= 1; mk >>= 1) {
            float so = __shfl_xor_sync(0xffffffffu, s,  mk);
            int   io = __shfl_xor_sync(0xffffffffu, id, mk);
            if (so < s || (so == s && io < id)) { s = so; id = io; }
        }
        if (tc == 0) sm.idx[tr * 8 + r] = id;
    }
    __syncthreads();

    // ---- gather codeword, out = fl(x + fl(q - x)), accumulate loss ----
    double lsum = 0.0;
    for (int i = tid; i < TM * 32; i += NTHREADS) {
        int tok = i >> 5;
        int d4  = i & 31;
        int id  = sm.idx[tok];
        float4 q = *reinterpret_cast<const float4*>(wg + (size_t)id * KD + d4 * 4);
        float x0 = sm.X[d4 * 4 + 0][tok];
        float x1 = sm.X[d4 * 4 + 1][tok];
        float x2 = sm.X[d4 * 4 + 2][tok];
        float x3 = sm.X[d4 * 4 + 3][tok];
        float e0 = __fsub_rn(q.x, x0), e1 = __fsub_rn(q.y, x1);
        float e2 = __fsub_rn(q.z, x2), e3 = __fsub_rn(q.w, x3);
        lsum += (double)e0 * e0 + (double)e1 * e1 + (double)e2 * e2 + (double)e3 * e3;
        float4 o;
        o.x = __fadd_rn(x0, e0); o.y = __fadd_rn(x1, e1);
        o.z = __fadd_rn(x2, e2); o.w = __fadd_rn(x3, e3);
        *reinterpret_cast<float4*>(
            out + (size_t)(t0blk + tok) * 512 + (size_t)g * KD + d4 * 4) = o;
    }

    #pragma unroll
    for (int mk = 16; mk >= 1; mk >>= 1)
        lsum += __shfl_down_sync(0xffffffffu, lsum, mk);
    if ((tid & 31) == 0) sm.lred[tid >> 5] = lsum;
    __syncthreads();
    if (tid == 0) {
        double t = 0.0;
        #pragma unroll
        for (int w = 0; w < NTHREADS / 32; w++) t += sm.lred[w];
        atomicAdd(&g_loss[g], t);
    }
}

__global__ void fin_kernel(float* __restrict__ out, int out_size, int T) {
    if (threadIdx.x == 0 && blockIdx.x == 0) {
        double s = 0.0;
        for (int g = 0; g < 4; g++) s += g_loss[g];
        double denom = (double)T * (double)KD;
        out[out_size - 1] = (float)(1.25 * s / denom);
    }
}

extern "C" void kernel_launch(void* const* d_in, const int* in_sizes, int n_in,
                              void* d_out, int out_size) {
    const float* lat = (const float*)d_in[0];
    const float* w1  = (const float*)d_in[1];
    const float* w2  = (const float*)d_in[2];
    const float* w3  = (const float*)d_in[3];
    const float* w4  = (const float*)d_in[4];
    float* out = (float*)d_out;
    const int T = in_sizes[0] / 512;

    size_t smem = sizeof(SMem);
    cudaFuncSetAttribute(vq_kernel, cudaFuncAttributeMaxDynamicSharedMemorySize, (int)smem);

    prep_kernel<<<8, 256>>>(w1, w2, w3, w4);

    dim3 grid(T / TM, 4);
    vq_kernel<<<grid, NTHREADS, smem>>>(lat, w1, w2, w3, w4, out);

    fin_kernel<<<1, 32>>>(out, out_size, T);
}

// round 6
// speedup vs baseline: 1.3552x; 1.3552x over previous
#include <cuda_runtime.h>
#include <cstdint>
#include <math.h>

// MultiVectorQuantizer: 4 groups, K=512 codes, D=128.
// Bit-replicates reference fp32 dist = fl(fl(x_sq+w_sq) - 2*cross) ordering via
// integer scores on the ulp(x_sq) grid. Exact rounding now via the magic-number
// trick: S = fmaf(acc, -sc2, m+M) == M + rne(m - z) exactly, because
// acc*sc2 is exact (pow2 scale), m is integer, and adding near M=1.5*2^23
// rounds half-even at ulp 1. Scores compared in half-units so the rare
// below-binade fine grid (ulp/2) is representable uniformly.

#define TM 128          // tokens per CTA
#define NC 64           // codes per chunk
#define KD 128
#define KCODES 512
#define NTHREADS 256    // 16 token-slots x 16 code-slots, 8x4 tile each
#define NBIN 10         // binade table rows: biased exp 128..137
#define MAGIC  12582912.0f    // 1.5*2^23
#define NEG2M -25165824.0f    // -2*MAGIC

__device__ double g_loss_part[8192];

struct SMem {
    float  X[KD][TM + 4];     // [d][token], stride 132
    float  W[KD][NC + 4];     // [d][code],  stride 68
    float  wsq[KCODES];       // exact sequential sum w^2 per code
    float  mM[NBIN][NC];      // M + rne(wsq*iU_e) per (binade,code), per chunk
    float  sc2[TM];           // 2^(24-E) per token
    float  tt02[TM];          // 2*(2^E - x_sq)/u  (integer-valued, <= 0)
    int    tb[TM];            // binade row 0..NBIN-1
    int    nearf[TM];         // 1 if dist may dip below 2^E
    int    idx[TM];
    double lred[8];
};

__global__ __launch_bounds__(NTHREADS, 2)
void vq_kernel(const float* __restrict__ lat,
               const float* __restrict__ w0, const float* __restrict__ w1,
               const float* __restrict__ w2, const float* __restrict__ w3,
               float* __restrict__ out) {
    extern __shared__ char smraw[];
    SMem& sm = *reinterpret_cast<SMem*>(smraw);

    const int g  = blockIdx.y;
    const int t0blk = blockIdx.x * TM;
    const float* __restrict__ wg = (g == 0) ? w0 : (g == 1) ? w1 : (g == 2) ? w2 : w3;
    const int tid = threadIdx.x;
    const int tc = tid & 15;        // code slot (4 codes)
    const int tr = tid >> 4;        // token slot (8 tokens)

    // ---- load X tile [128 tok x 128 d] -> transposed smem ----
    for (int i = tid; i < TM * 32; i += NTHREADS) {
        int tok = i >> 5;
        int d4  = i & 31;
        float4 v = *reinterpret_cast<const float4*>(
            lat + (size_t)(t0blk + tok) * 512 + (size_t)g * KD + d4 * 4);
        sm.X[d4 * 4 + 0][tok] = v.x;
        sm.X[d4 * 4 + 1][tok] = v.y;
        sm.X[d4 * 4 + 2][tok] = v.z;
        sm.X[d4 * 4 + 3][tok] = v.w;
    }

    // ---- per-CTA wsq: exact sequential mul-then-add per code (from L2) ----
    for (int kc = tid; kc < KCODES; kc += NTHREADS) {
        const float4* row = reinterpret_cast<const float4*>(wg + (size_t)kc * KD);
        float s = 0.f;
        #pragma unroll 8
        for (int d4 = 0; d4 < KD / 4; d4++) {
            float4 v = row[d4];
            s = __fadd_rn(s, __fmul_rn(v.x, v.x));
            s = __fadd_rn(s, __fmul_rn(v.y, v.y));
            s = __fadd_rn(s, __fmul_rn(v.z, v.z));
            s = __fadd_rn(s, __fmul_rn(v.w, v.w));
        }
        sm.wsq[kc] = s;
    }
    __syncthreads();

    // ---- per-token binade constants ----
    if (tid < TM) {
        float s = 0.f;
        #pragma unroll 8
        for (int d = 0; d < KD; d++) {
            float v = sm.X[d][tid];
            s = fmaf(v, v, s);                      // only binade matters
        }
        uint32_t b  = __float_as_uint(s);
        uint32_t be = (b >> 23) & 0xFF;             // biased exponent
        int tbv = (int)be - 128;
        tbv = tbv < 0 ? 0 : (tbv > NBIN - 1 ? NBIN - 1 : tbv);
        sm.tb[tid]  = tbv;
        sm.sc2[tid] = __uint_as_float((278u - be) << 23);    // 2^(24-E)
        float iU    = __uint_as_float((277u - be) << 23);    // 2^(23-E)
        float pw    = __uint_as_float(be << 23);             // 2^E
        float t0u   = __fmul_rn(__fsub_rn(pw, s), iU);       // exact int <= 0
        sm.tt02[tid] = __fadd_rn(t0u, t0u);
        // near: dist can dip below 2^E only if x_sq - 2^E < 2|x||w|max + slack
        float margin = fmaf(0.0451f, sqrtf(s), 0.004f);
        sm.nearf[tid] = (__fsub_rn(s, pw) < margin) ? 1 : 0;
    }

    // per-thread token-row constants (loaded after first chunk sync)
    int tokr[8];
    #pragma unroll
    for (int r = 0; r < 8; r++)
        tokr[r] = (r < 4) ? (tr * 4 + r) : (64 + tr * 4 + (r - 4));
    float sc2r[8], tt02r[8];
    const float4* mMp[8];
    int nearmask = 0;

    float best[8];
    int   bidx[8];
    #pragma unroll
    for (int r = 0; r < 8; r++) { best[r] = 3.4e38f; bidx[r] = 0; }
    bool got_const = false;

    for (int c = 0; c < KCODES / NC; c++) {
        __syncthreads();
        if (!got_const) {
            #pragma unroll
            for (int r = 0; r < 8; r++) {
                int tk = tokr[r];
                sc2r[r]  = sm.sc2[tk];
                tt02r[r] = sm.tt02[tk];
                mMp[r]   = reinterpret_cast<const float4*>(&sm.mM[sm.tb[tk]][tc * 4]);
                nearmask |= sm.nearf[tk] << r;
            }
            got_const = true;
        }
        // ---- load W chunk [64 codes x 128 d] -> transposed smem ----
        for (int i = tid; i < NC * 32; i += NTHREADS) {
            int n  = i >> 5;
            int d4 = i & 31;
            float4 v = *reinterpret_cast<const float4*>(
                wg + (size_t)(c * NC + n) * KD + d4 * 4);
            sm.W[d4 * 4 + 0][n] = v.x;
            sm.W[d4 * 4 + 1][n] = v.y;
            sm.W[d4 * 4 + 2][n] = v.z;
            sm.W[d4 * 4 + 3][n] = v.w;
        }
        // ---- mM table: M + rne(wsq*iU_e) for all binade rows ----
        for (int i = tid; i < NBIN * NC; i += NTHREADS) {
            int row = i >> 6;
            int j   = i & (NC - 1);
            float iU = __uint_as_float((uint32_t)(149 - row) << 23);  // 2^(22-row)
            sm.mM[row][j] = fmaf(sm.wsq[c * NC + j], iU, MAGIC);      // exact prod
        }
        __syncthreads();

        // ---- 8x4 register-tile GEMM, sequential FMA over d (matches ref) ----
        float acc[8][4];
        #pragma unroll
        for (int r = 0; r < 8; r++)
            #pragma unroll
            for (int j = 0; j < 4; j++) acc[r][j] = 0.f;

        #pragma unroll 4
        for (int k = 0; k < KD; k++) {
            float4 a0 = *reinterpret_cast<const float4*>(&sm.X[k][tr * 4]);
            float4 a1 = *reinterpret_cast<const float4*>(&sm.X[k][64 + tr * 4]);
            float4 bb = *reinterpret_cast<const float4*>(&sm.W[k][tc * 4]);
            float ai[8] = {a0.x, a0.y, a0.z, a0.w, a1.x, a1.y, a1.z, a1.w};
            float bj[4] = {bb.x, bb.y, bb.z, bb.w};
            #pragma unroll
            for (int r = 0; r < 8; r++)
                #pragma unroll
                for (int j = 0; j < 4; j++)
                    acc[r][j] = fmaf(ai[r], bj[j], acc[r][j]);
        }

        // ---- scoring: S = M + rne(m - z) in ONE exact FMA; half-unit scale ----
        const int kgbase = c * NC + tc * 4;
        #pragma unroll
        for (int r = 0; r < 8; r++) {
            float4 mm  = *mMp[r];                     // mM row, 4 codes
            float nsc2 = -sc2r[r];
            float S0 = fmaf(acc[r][0], nsc2, mm.x);
            float S1 = fmaf(acc[r][1], nsc2, mm.y);
            float S2 = fmaf(acc[r][2], nsc2, mm.z);
            float S3 = fmaf(acc[r][3], nsc2, mm.w);
            float s0 = fmaf(S0, 2.f, NEG2M);          // 2*rne(m-z), exact
            float s1 = fmaf(S1, 2.f, NEG2M);
            float s2 = fmaf(S2, 2.f, NEG2M);
            float s3 = fmaf(S3, 2.f, NEG2M);
            if (nearmask & (1 << r)) {                // rare: fine grid below 2^E
                float tt02 = tt02r[r];
                float nsc4 = __fadd_rn(nsc2, nsc2);
                float m2, Sf, sf2;
                m2 = fmaf(2.f, mm.x, -MAGIC);         // M + 2m, exact
                Sf = fmaf(acc[r][0], nsc4, m2);       // M + rne(2m-2z), exact
                sf2 = __fsub_rn(Sf, MAGIC);
                if (sf2 < tt02) s0 = sf2;
                m2 = fmaf(2.f, mm.y, -MAGIC);
                Sf = fmaf(acc[r][1], nsc4, m2);
                sf2 = __fsub_rn(Sf, MAGIC);
                if (sf2 < tt02) s1 = sf2;
                m2 = fmaf(2.f, mm.z, -MAGIC);
                Sf = fmaf(acc[r][2], nsc4, m2);
                sf2 = __fsub_rn(Sf, MAGIC);
                if (sf2 < tt02) s2 = sf2;
                m2 = fmaf(2.f, mm.w, -MAGIC);
                Sf = fmaf(acc[r][3], nsc4, m2);
                sf2 = __fsub_rn(Sf, MAGIC);
                if (sf2 < tt02) s3 = sf2;
            }
            // min tree, lowest index wins ties
            float mA = s0; int jA = 0;
            if (s1 < mA) { mA = s1; jA = 1; }
            float mB = s2; int jB = 2;
            if (s3 < mB) { mB = s3; jB = 3; }
            if (mB < mA) { mA = mB; jA = jB; }
            if (mA < best[r]) { best[r] = mA; bidx[r] = kgbase + jA; }
        }
    }

    // ---- argmin reduce across 16 tc-lanes (lowest index on ties) ----
    #pragma unroll
    for (int r = 0; r < 8; r++) {
        float s  = best[r];
        int   id = bidx[r];
        #pragma unroll
        for (int mk = 8; mk >= 1; mk >>= 1) {
            float so = __shfl_xor_sync(0xffffffffu, s,  mk);
            int   io = __shfl_xor_sync(0xffffffffu, id, mk);
            if (so < s || (so == s && io < id)) { s = so; id = io; }
        }
        if (tc == 0) sm.idx[tokr[r]] = id;
    }
    __syncthreads();

    // ---- gather codeword, out = fl(x + fl(q - x)), accumulate loss ----
    double lsum = 0.0;
    for (int i = tid; i < TM * 32; i += NTHREADS) {
        int tok = i >> 5;
        int d4  = i & 31;
        int id  = sm.idx[tok];
        float4 q = *reinterpret_cast<const float4*>(wg + (size_t)id * KD + d4 * 4);
        float x0 = sm.X[d4 * 4 + 0][tok];
        float x1 = sm.X[d4 * 4 + 1][tok];
        float x2 = sm.X[d4 * 4 + 2][tok];
        float x3 = sm.X[d4 * 4 + 3][tok];
        float e0 = __fsub_rn(q.x, x0), e1 = __fsub_rn(q.y, x1);
        float e2 = __fsub_rn(q.z, x2), e3 = __fsub_rn(q.w, x3);
        lsum += (double)e0 * e0 + (double)e1 * e1 + (double)e2 * e2 + (double)e3 * e3;
        float4 o;
        o.x = __fadd_rn(x0, e0); o.y = __fadd_rn(x1, e1);
        o.z = __fadd_rn(x2, e2); o.w = __fadd_rn(x3, e3);
        *reinterpret_cast<float4*>(
            out + (size_t)(t0blk + tok) * 512 + (size_t)g * KD + d4 * 4) = o;
    }

    #pragma unroll
    for (int mk = 16; mk >= 1; mk >>= 1)
        lsum += __shfl_down_sync(0xffffffffu, lsum, mk);
    if ((tid & 31) == 0) sm.lred[tid >> 5] = lsum;
    __syncthreads();
    if (tid == 0) {
        double t = 0.0;
        #pragma unroll
        for (int w = 0; w < NTHREADS / 32; w++) t += sm.lred[w];
        g_loss_part[blockIdx.y * gridDim.x + blockIdx.x] = t;
    }
}

__global__ void fin_kernel(float* __restrict__ out, int out_size, int T, int nslots) {
    __shared__ double red[8];
    int tid = threadIdx.x;
    double s = 0.0;
    for (int i = tid; i < nslots; i += 256) s += g_loss_part[i];
    #pragma unroll
    for (int mk = 16; mk >= 1; mk >>= 1)
        s += __shfl_down_sync(0xffffffffu, s, mk);
    if ((tid & 31) == 0) red[tid >> 5] = s;
    __syncthreads();
    if (tid == 0) {
        double t = 0.0;
        #pragma unroll
        for (int w = 0; w < 8; w++) t += red[w];
        double denom = (double)T * (double)KD;
        out[out_size - 1] = (float)(1.25 * t / denom);
    }
}

extern "C" void kernel_launch(void* const* d_in, const int* in_sizes, int n_in,
                              void* d_out, int out_size) {
    const float* lat = (const float*)d_in[0];
    const float* w1  = (const float*)d_in[1];
    const float* w2  = (const float*)d_in[2];
    const float* w3  = (const float*)d_in[3];
    const float* w4  = (const float*)d_in[4];
    float* out = (float*)d_out;
    const int T = in_sizes[0] / 512;

    size_t smem = sizeof(SMem);
    cudaFuncSetAttribute(vq_kernel, cudaFuncAttributeMaxDynamicSharedMemorySize, (int)smem);

    dim3 grid(T / TM, 4);
    vq_kernel<<<grid, NTHREADS, smem>>>(lat, w1, w2, w3, w4, out);

    fin_kernel<<<1, 256>>>(out, out_size, T, (T / TM) * 4);
}

// round 10
// speedup vs baseline: 1.3710x; 1.0116x over previous
#include <cuda_runtime.h>
#include <cstdint>
#include <math.h>

// MultiVectorQuantizer: 4 groups, K=512 codes, D=128.
// R6 scoring framework (integer scores on the ulp(x_sq) grid, magic-number
// exact RHE, rel_err 0.0) + FFMA2 (fma.rn.f32x2) GEMM with token-paired lanes.
// Each 32-bit lane of FFMA2 computes rn(a*b+c) independently in the same
// k-order -> acc bits identical to the scalar R6 kernel.

#define TM 128          // tokens per CTA
#define NC 64           // codes per chunk
#define KD 128
#define KCODES 512
#define NTHREADS 256    // 16 token-slots x 16 code-slots, 8x4 tile each
#define NBIN 10
#define MAGIC  12582912.0f    // 1.5*2^23
#define NEG2M -25165824.0f    // -2*MAGIC

typedef unsigned long long ull;

__device__ double g_loss_part[8192];

struct SMem {
    float  X[KD][TM + 4];     // [d][token], stride 132
    float  W[KD][NC + 4];     // [d][code],  stride 68
    float  wsq[KCODES];
    float  mM[NBIN][NC];      // M + rne(wsq*iU_e), per chunk
    float  sc2[TM];           // 2^(24-E)
    float  tt02[TM];          // 2*(2^E - x_sq)/u
    int    tb[TM];
    int    nearf[TM];
    int    idx[TM];
    double lred[8];
};

__device__ __forceinline__ ull pk2(float lo, float hi) {
    ull r;
    asm("mov.b64 %0, {%1,%2};" : "=l"(r) : "f"(lo), "f"(hi));
    return r;
}
__device__ __forceinline__ void upk2(float& lo, float& hi, ull v) {
    asm("mov.b64 {%0,%1}, %2;" : "=f"(lo), "=f"(hi) : "l"(v));
}
__device__ __forceinline__ void fma2(ull& acc, ull a, ull b) {
    asm("fma.rn.f32x2 %0, %1, %2, %0;" : "+l"(acc) : "l"(a), "l"(b));
}

__global__ __launch_bounds__(NTHREADS, 2)
void vq_kernel(const float* __restrict__ lat,
               const float* __restrict__ w0, const float* __restrict__ w1,
               const float* __restrict__ w2, const float* __restrict__ w3,
               float* __restrict__ out) {
    extern __shared__ char smraw[];
    SMem& sm = *reinterpret_cast<SMem*>(smraw);

    const int g  = blockIdx.y;
    const int t0blk = blockIdx.x * TM;
    const float* __restrict__ wg = (g == 0) ? w0 : (g == 1) ? w1 : (g == 2) ? w2 : w3;
    const int tid = threadIdx.x;
    const int tc = tid & 15;        // code slot (4 codes)
    const int tr = tid >> 4;        // token slot (8 tokens = 4 lane-pairs)

    // ---- load X tile -> transposed smem ----
    for (int i = tid; i < TM * 32; i += NTHREADS) {
        int tok = i >> 5;
        int d4  = i & 31;
        float4 v = *reinterpret_cast<const float4*>(
            lat + (size_t)(t0blk + tok) * 512 + (size_t)g * KD + d4 * 4);
        sm.X[d4 * 4 + 0][tok] = v.x;
        sm.X[d4 * 4 + 1][tok] = v.y;
        sm.X[d4 * 4 + 2][tok] = v.z;
        sm.X[d4 * 4 + 3][tok] = v.w;
    }

    // ---- per-CTA wsq: exact sequential mul-then-add per code ----
    for (int kc = tid; kc < KCODES; kc += NTHREADS) {
        const float4* row = reinterpret_cast<const float4*>(wg + (size_t)kc * KD);
        float s = 0.f;
        #pragma unroll 8
        for (int d4 = 0; d4 < KD / 4; d4++) {
            float4 v = row[d4];
            s = __fadd_rn(s, __fmul_rn(v.x, v.x));
            s = __fadd_rn(s, __fmul_rn(v.y, v.y));
            s = __fadd_rn(s, __fmul_rn(v.z, v.z));
            s = __fadd_rn(s, __fmul_rn(v.w, v.w));
        }
        sm.wsq[kc] = s;
    }
    __syncthreads();

    // ---- per-token binade constants ----
    if (tid < TM) {
        float s = 0.f;
        #pragma unroll 8
        for (int d = 0; d < KD; d++) {
            float v = sm.X[d][tid];
            s = fmaf(v, v, s);
        }
        uint32_t b  = __float_as_uint(s);
        uint32_t be = (b >> 23) & 0xFF;
        int tbv = (int)be - 128;
        tbv = tbv < 0 ? 0 : (tbv > NBIN - 1 ? NBIN - 1 : tbv);
        sm.tb[tid]  = tbv;
        sm.sc2[tid] = __uint_as_float((278u - be) << 23);
        float iU    = __uint_as_float((277u - be) << 23);
        float pw    = __uint_as_float(be << 23);
        float t0u   = __fmul_rn(__fsub_rn(pw, s), iU);
        sm.tt02[tid] = __fadd_rn(t0u, t0u);
        float margin = fmaf(0.0451f, sqrtf(s), 0.004f);
        sm.nearf[tid] = (__fsub_rn(s, pw) < margin) ? 1 : 0;
    }

    int tokr[8];
    #pragma unroll
    for (int r = 0; r < 8; r++)
        tokr[r] = (r < 4) ? (tr * 4 + r) : (64 + tr * 4 + (r - 4));
    float sc2r[8], tt02r[8];
    const float4* mMp[8];
    int nearmask = 0;

    float best[8];
    int   bidx[8];
    #pragma unroll
    for (int r = 0; r < 8; r++) { best[r] = 3.4e38f; bidx[r] = 0; }
    bool got_const = false;

    for (int c = 0; c < KCODES / NC; c++) {
        __syncthreads();
        if (!got_const) {
            #pragma unroll
            for (int r = 0; r < 8; r++) {
                int tk = tokr[r];
                sc2r[r]  = sm.sc2[tk];
                tt02r[r] = sm.tt02[tk];
                mMp[r]   = reinterpret_cast<const float4*>(&sm.mM[sm.tb[tk]][tc * 4]);
                nearmask |= sm.nearf[tk] << r;
            }
            got_const = true;
        }
        // ---- load W chunk -> transposed smem ----
        for (int i = tid; i < NC * 32; i += NTHREADS) {
            int n  = i >> 5;
            int d4 = i & 31;
            float4 v = *reinterpret_cast<const float4*>(
                wg + (size_t)(c * NC + n) * KD + d4 * 4);
            sm.W[d4 * 4 + 0][n] = v.x;
            sm.W[d4 * 4 + 1][n] = v.y;
            sm.W[d4 * 4 + 2][n] = v.z;
            sm.W[d4 * 4 + 3][n] = v.w;
        }
        // ---- mM table: M + rne(wsq*iU_e) for all binade rows ----
        for (int i = tid; i < NBIN * NC; i += NTHREADS) {
            int row = i >> 6;
            int j   = i & (NC - 1);
            float iU = __uint_as_float((uint32_t)(149 - row) << 23);
            sm.mM[row][j] = fmaf(sm.wsq[c * NC + j], iU, MAGIC);
        }
        __syncthreads();

        // ---- 8x4 tile via FFMA2, token pairs in lanes; same k-order ----
        ull acc2[4][4];
        #pragma unroll
        for (int p = 0; p < 4; p++)
            #pragma unroll
            for (int j = 0; j < 4; j++) acc2[p][j] = 0ull;

        const float* xk = &sm.X[0][tr * 4];
        const float* wk = &sm.W[0][tc * 4];
        #pragma unroll 4
        for (int k = 0; k < KD; k++) {
            ulonglong2 av0 = *reinterpret_cast<const ulonglong2*>(xk);        // tok pairs 0,1
            ulonglong2 av1 = *reinterpret_cast<const ulonglong2*>(xk + 64);   // tok pairs 2,3
            float4 bb = *reinterpret_cast<const float4*>(wk);
            xk += TM + 4;
            wk += NC + 4;
            ull A[4] = {av0.x, av0.y, av1.x, av1.y};
            ull B[4] = {pk2(bb.x, bb.x), pk2(bb.y, bb.y),
                        pk2(bb.z, bb.z), pk2(bb.w, bb.w)};
            #pragma unroll
            for (int p = 0; p < 4; p++)
                #pragma unroll
                for (int j = 0; j < 4; j++)
                    fma2(acc2[p][j], A[p], B[j]);
        }

        // ---- scoring: S = M + rne(m - z) in ONE exact FMA; half-unit scale ----
        const int kgbase = c * NC + tc * 4;
        #pragma unroll
        for (int p = 0; p < 4; p++) {
            #pragma unroll
            for (int h = 0; h < 2; h++) {
                int r = 2 * p + h;     // tokr index: pair p, lane h
                float a0, a1, a2, a3, dummy;
                if (h == 0) { upk2(a0, dummy, acc2[p][0]); upk2(a1, dummy, acc2[p][1]);
                              upk2(a2, dummy, acc2[p][2]); upk2(a3, dummy, acc2[p][3]); }
                else        { upk2(dummy, a0, acc2[p][0]); upk2(dummy, a1, acc2[p][1]);
                              upk2(dummy, a2, acc2[p][2]); upk2(dummy, a3, acc2[p][3]); }
                float4 mm  = *mMp[r];
                float nsc2 = -sc2r[r];
                float S0 = fmaf(a0, nsc2, mm.x);
                float S1 = fmaf(a1, nsc2, mm.y);
                float S2 = fmaf(a2, nsc2, mm.z);
                float S3 = fmaf(a3, nsc2, mm.w);
                float s0 = fmaf(S0, 2.f, NEG2M);
                float s1 = fmaf(S1, 2.f, NEG2M);
                float s2 = fmaf(S2, 2.f, NEG2M);
                float s3 = fmaf(S3, 2.f, NEG2M);
                if (nearmask & (1 << r)) {            // rare: fine grid below 2^E
                    float tt02 = tt02r[r];
                    float nsc4 = __fadd_rn(nsc2, nsc2);
                    float m2, Sf, sf2;
                    m2 = fmaf(2.f, mm.x, -MAGIC);
                    Sf = fmaf(a0, nsc4, m2);
                    sf2 = __fsub_rn(Sf, MAGIC);
                    if (sf2 < tt02) s0 = sf2;
                    m2 = fmaf(2.f, mm.y, -MAGIC);
                    Sf = fmaf(a1, nsc4, m2);
                    sf2 = __fsub_rn(Sf, MAGIC);
                    if (sf2 < tt02) s1 = sf2;
                    m2 = fmaf(2.f, mm.z, -MAGIC);
                    Sf = fmaf(a2, nsc4, m2);
                    sf2 = __fsub_rn(Sf, MAGIC);
                    if (sf2 < tt02) s2 = sf2;
                    m2 = fmaf(2.f, mm.w, -MAGIC);
                    Sf = fmaf(a3, nsc4, m2);
                    sf2 = __fsub_rn(Sf, MAGIC);
                    if (sf2 < tt02) s3 = sf2;
                }
                float mA = s0; int jA = 0;
                if (s1 < mA) { mA = s1; jA = 1; }
                float mB = s2; int jB = 2;
                if (s3 < mB) { mB = s3; jB = 3; }
                if (mB < mA) { mA = mB; jA = jB; }
                if (mA < best[r]) { best[r] = mA; bidx[r] = kgbase + jA; }
            }
        }
    }

    // ---- argmin reduce across 16 tc-lanes (lowest index on ties) ----
    // acc lane layout: pair p=0 -> tokens tr*4+0 (lo), tr*4+1 (hi); p=1 ->
    // tr*4+2/3; p=2 -> 64+tr*4+0/1; p=3 -> 64+tr*4+2/3.  (== tokr[r])
    int tokmap[8];
    #pragma unroll
    for (int p = 0; p < 4; p++) {
        int base = (p < 2) ? (tr * 4 + p * 2) : (64 + tr * 4 + (p - 2) * 2);
        tokmap[2 * p + 0] = base;
        tokmap[2 * p + 1] = base + 1;
    }
    #pragma unroll
    for (int r = 0; r < 8; r++) {
        float s  = best[r];
        int   id = bidx[r];
        #pragma unroll
        for (int mk = 8; mk >= 1; mk >>= 1) {
            float so = __shfl_xor_sync(0xffffffffu, s,  mk);
            int   io = __shfl_xor_sync(0xffffffffu, id, mk);
            if (so < s || (so == s && io < id)) { s = so; id = io; }
        }
        if (tc == 0) sm.idx[tokmap[r]] = id;
    }
    __syncthreads();

    // ---- gather codeword, out = fl(x + fl(q - x)), accumulate loss ----
    double lsum = 0.0;
    for (int i = tid; i < TM * 32; i += NTHREADS) {
        int tok = i >> 5;
        int d4  = i & 31;
        int id  = sm.idx[tok];
        float4 q = *reinterpret_cast<const float4*>(wg + (size_t)id * KD + d4 * 4);
        float x0 = sm.X[d4 * 4 + 0][tok];
        float x1 = sm.X[d4 * 4 + 1][tok];
        float x2 = sm.X[d4 * 4 + 2][tok];
        float x3 = sm.X[d4 * 4 + 3][tok];
        float e0 = __fsub_rn(q.x, x0), e1 = __fsub_rn(q.y, x1);
        float e2 = __fsub_rn(q.z, x2), e3 = __fsub_rn(q.w, x3);
        lsum += (double)e0 * e0 + (double)e1 * e1 + (double)e2 * e2 + (double)e3 * e3;
        float4 o;
        o.x = __fadd_rn(x0, e0); o.y = __fadd_rn(x1, e1);
        o.z = __fadd_rn(x2, e2); o.w = __fadd_rn(x3, e3);
        *reinterpret_cast<float4*>(
            out + (size_t)(t0blk + tok) * 512 + (size_t)g * KD + d4 * 4) = o;
    }

    #pragma unroll
    for (int mk = 16; mk >= 1; mk >>= 1)
        lsum += __shfl_down_sync(0xffffffffu, lsum, mk);
    if ((tid & 31) == 0) sm.lred[tid >> 5] = lsum;
    __syncthreads();
    if (tid == 0) {
        double t = 0.0;
        #pragma unroll
        for (int w = 0; w < NTHREADS / 32; w++) t += sm.lred[w];
        g_loss_part[blockIdx.y * gridDim.x + blockIdx.x] = t;
    }
}

__global__ void fin_kernel(float* __restrict__ out, int out_size, int T, int nslots) {
    __shared__ double red[8];
    int tid = threadIdx.x;
    double s = 0.0;
    for (int i = tid; i < nslots; i += 256) s += g_loss_part[i];
    #pragma unroll
    for (int mk = 16; mk >= 1; mk >>= 1)
        s += __shfl_down_sync(0xffffffffu, s, mk);
    if ((tid & 31) == 0) red[tid >> 5] = s;
    __syncthreads();
    if (tid == 0) {
        double t = 0.0;
        #pragma unroll
        for (int w = 0; w < 8; w++) t += red[w];
        double denom = (double)T * (double)KD;
        out[out_size - 1] = (float)(1.25 * t / denom);
    }
}

extern "C" void kernel_launch(void* const* d_in, const int* in_sizes, int n_in,
                              void* d_out, int out_size) {
    const float* lat = (const float*)d_in[0];
    const float* w1  = (const float*)d_in[1];
    const float* w2  = (const float*)d_in[2];
    const float* w3  = (const float*)d_in[3];
    const float* w4  = (const float*)d_in[4];
    float* out = (float*)d_out;
    const int T = in_sizes[0] / 512;

    size_t smem = sizeof(SMem);
    cudaFuncSetAttribute(vq_kernel, cudaFuncAttributeMaxDynamicSharedMemorySize, (int)smem);

    dim3 grid(T / TM, 4);
    vq_kernel<<<grid, NTHREADS, smem>>>(lat, w1, w2, w3, w4, out);

    fin_kernel<<<1, 256>>>(out, out_size, T, (T / TM) * 4);
}